// round 14
// baseline (speedup 1.0000x reference)
#include <cuda_runtime.h>
#include <cstdint>

#define SEQ    2048
#define BATCH  4096
#define IN     4
#define HID    3
#define UNR    8                   // timesteps per pipeline stage
#define STAGES 4                   // smem pipeline depth (32 KB)
#define NGRP   (SEQ / UNR)         // 256 groups
#define NPAIR  (BATCH / 2)         // 2048 chain pairs

typedef unsigned long long u64;

// ---- packed f32x2 helpers (Blackwell) ----
__device__ __forceinline__ u64 pack2(float lo, float hi) {
    u64 r; asm("mov.b64 %0, {%1, %2};" : "=l"(r) : "f"(lo), "f"(hi)); return r;
}
__device__ __forceinline__ u64 bcast2(float v) {
    u64 r; asm("mov.b64 %0, {%1, %1};" : "=l"(r) : "f"(v)); return r;
}
__device__ __forceinline__ u64 fma2(u64 a, u64 b, u64 c) {
    u64 d; asm("fma.rn.f32x2 %0, %1, %2, %3;" : "=l"(d) : "l"(a), "l"(b), "l"(c)); return d;
}
__device__ __forceinline__ float2 unpack2(u64 v) {
    float2 r; asm("mov.b64 {%0, %1}, %2;" : "=f"(r.x), "=f"(r.y) : "l"(v)); return r;
}

// ---- cp.async ----
__device__ __forceinline__ void cp_async16(void* smem_dst, const void* gmem_src) {
    uint32_t s;
    asm("{ .reg .u64 t; cvta.to.shared.u64 t, %1; cvt.u32.u64 %0, t; }"
        : "=r"(s) : "l"(smem_dst));
    asm volatile("cp.async.ca.shared.global [%0], [%1], 16;"
                 :: "r"(s), "l"(gmem_src) : "memory");
}
__device__ __forceinline__ void cp_async_commit() {
    asm volatile("cp.async.commit_group;" ::: "memory");
}
template <int N>
__device__ __forceinline__ void cp_async_wait() {
    asm volatile("cp.async.wait_group %0;" :: "n"(N) : "memory");
}

__global__ void __launch_bounds__(32, 1)
rnn_relu_kernel(const float* __restrict__ x,      // [SEQ, BATCH, 4]
                const float* __restrict__ h0,     // [1, BATCH, 3]
                const float* __restrict__ W_ih,   // [3, 4]
                const float* __restrict__ W_hh,   // [3, 3]
                const float* __restrict__ b_ih,   // [3]
                const float* __restrict__ b_hh,   // [3]
                float* __restrict__ out)
{
    // One warp/block; each thread owns chains (2p, 2p+1). Sync-free.
    // Chain-major-then-lane layout: LDS lane stride = 16 B -> conflict-free.
    __shared__ float4 xs[STAGES][UNR][2][32];   // 32 KB

    const int lane = threadIdx.x;
    const int p  = blockIdx.x * 32 + lane;   // pair index
    const int bA = 2 * p;                    // chain A; chain B = bA+1

    // Projection weights pre-broadcast (per-iter cost zero).
    u64 wP[HID][IN];
    u64 biasP[HID];
#pragma unroll
    for (int j = 0; j < HID; j++) {
#pragma unroll
        for (int i = 0; i < IN; i++) wP[j][i] = bcast2(W_ih[j * IN + i]);
        biasP[j] = bcast2(b_ih[j] + b_hh[j]);
    }
    // Recurrence weights scalar (16-cyc chain per step, no movs on chain).
    float whh[HID][HID];
#pragma unroll
    for (int j = 0; j < HID; j++)
#pragma unroll
        for (int i = 0; i < HID; i++) whh[j][i] = W_hh[j * HID + i];

    float hA0 = h0[bA * HID + 0], hA1 = h0[bA * HID + 1], hA2 = h0[bA * HID + 2];
    float hB0 = h0[bA * HID + 3], hB1 = h0[bA * HID + 4], hB2 = h0[bA * HID + 5];

    const float4* __restrict__ xv = (const float4*)x;  // [SEQ][BATCH]
    float* __restrict__ outs  = out;
    float* __restrict__ hlast = out + (size_t)SEQ * BATCH * HID;

    // Prime 3 stages (24 timesteps lookahead, both chains; 32 B contiguous/lane).
#pragma unroll
    for (int s = 0; s < STAGES - 1; s++) {
#pragma unroll
        for (int k = 0; k < UNR; k++) {
            const size_t src = (size_t)(s * UNR + k) * BATCH + bA;
            cp_async16(&xs[s][k][0][lane], &xv[src]);
            cp_async16(&xs[s][k][1][lane], &xv[src + 1]);
        }
        cp_async_commit();
    }

    for (int g = 0; g < NGRP; g++) {
        const int stage = g & (STAGES - 1);
        cp_async_wait<STAGES - 2>();   // this stage complete (self-written smem)

        const int t0 = g * UNR;
#pragma unroll
        for (int k = 0; k < UNR; k += 2) {
            // x for 2 timesteps x 2 chains (4 conflict-free LDS.128).
            const float4 xa0 = xs[stage][k + 0][0][lane];
            const float4 xb0 = xs[stage][k + 0][1][lane];
            const float4 xa1 = xs[stage][k + 1][0][lane];
            const float4 xb1 = xs[stage][k + 1][1][lane];

            // ---- time-packed projections, chain A then B (all off-chain) ----
            const u64 axx = pack2(xa0.x, xa1.x);
            const u64 axy = pack2(xa0.y, xa1.y);
            const u64 axz = pack2(xa0.z, xa1.z);
            const u64 axw = pack2(xa0.w, xa1.w);
            u64 PA0 = fma2(wP[0][0], axx, biasP[0]);
            u64 PA1 = fma2(wP[1][0], axx, biasP[1]);
            u64 PA2 = fma2(wP[2][0], axx, biasP[2]);
            PA0 = fma2(wP[0][1], axy, PA0);
            PA1 = fma2(wP[1][1], axy, PA1);
            PA2 = fma2(wP[2][1], axy, PA2);
            PA0 = fma2(wP[0][2], axz, PA0);
            PA1 = fma2(wP[1][2], axz, PA1);
            PA2 = fma2(wP[2][2], axz, PA2);
            PA0 = fma2(wP[0][3], axw, PA0);
            PA1 = fma2(wP[1][3], axw, PA1);
            PA2 = fma2(wP[2][3], axw, PA2);

            const u64 bxx = pack2(xb0.x, xb1.x);
            const u64 bxy = pack2(xb0.y, xb1.y);
            const u64 bxz = pack2(xb0.z, xb1.z);
            const u64 bxw = pack2(xb0.w, xb1.w);
            u64 PB0 = fma2(wP[0][0], bxx, biasP[0]);
            u64 PB1 = fma2(wP[1][0], bxx, biasP[1]);
            u64 PB2 = fma2(wP[2][0], bxx, biasP[2]);
            PB0 = fma2(wP[0][1], bxy, PB0);
            PB1 = fma2(wP[1][1], bxy, PB1);
            PB2 = fma2(wP[2][1], bxy, PB2);
            PB0 = fma2(wP[0][2], bxz, PB0);
            PB1 = fma2(wP[1][2], bxz, PB1);
            PB2 = fma2(wP[2][2], bxz, PB2);
            PB0 = fma2(wP[0][3], bxw, PB0);
            PB1 = fma2(wP[1][3], bxw, PB1);
            PB2 = fma2(wP[2][3], bxw, PB2);

            const float2 qA0 = unpack2(PA0), qA1 = unpack2(PA1), qA2 = unpack2(PA2);
            const float2 qB0 = unpack2(PB0), qB1 = unpack2(PB1), qB2 = unpack2(PB2);

            // ---- timestep t: chains A and B interleave (independent chains) ----
            {
                float a0 = fmaf(whh[0][0], hA0, qA0.x);
                float a1 = fmaf(whh[1][0], hA0, qA1.x);
                float a2 = fmaf(whh[2][0], hA0, qA2.x);
                float c0 = fmaf(whh[0][0], hB0, qB0.x);
                float c1 = fmaf(whh[1][0], hB0, qB1.x);
                float c2 = fmaf(whh[2][0], hB0, qB2.x);
                a0 = fmaf(whh[0][1], hA1, a0);
                a1 = fmaf(whh[1][1], hA1, a1);
                a2 = fmaf(whh[2][1], hA1, a2);
                c0 = fmaf(whh[0][1], hB1, c0);
                c1 = fmaf(whh[1][1], hB1, c1);
                c2 = fmaf(whh[2][1], hB1, c2);
                a0 = fmaf(whh[0][2], hA2, a0);
                a1 = fmaf(whh[1][2], hA2, a1);
                a2 = fmaf(whh[2][2], hA2, a2);
                c0 = fmaf(whh[0][2], hB2, c0);
                c1 = fmaf(whh[1][2], hB2, c1);
                c2 = fmaf(whh[2][2], hB2, c2);

                hA0 = fmaxf(a0, 0.0f); hA1 = fmaxf(a1, 0.0f); hA2 = fmaxf(a2, 0.0f);
                hB0 = fmaxf(c0, 0.0f); hB1 = fmaxf(c1, 0.0f); hB2 = fmaxf(c2, 0.0f);

                const size_t o = ((size_t)(t0 + k) * BATCH + bA) * HID;  // 8B-aligned
                __stcs((float2*)(outs + o),     make_float2(hA0, hA1));
                __stcs((float2*)(outs + o + 2), make_float2(hA2, hB0));
                __stcs((float2*)(outs + o + 4), make_float2(hB1, hB2));
            }

            // ---- timestep t+1 ----
            {
                float a0 = fmaf(whh[0][0], hA0, qA0.y);
                float a1 = fmaf(whh[1][0], hA0, qA1.y);
                float a2 = fmaf(whh[2][0], hA0, qA2.y);
                float c0 = fmaf(whh[0][0], hB0, qB0.y);
                float c1 = fmaf(whh[1][0], hB0, qB1.y);
                float c2 = fmaf(whh[2][0], hB0, qB2.y);
                a0 = fmaf(whh[0][1], hA1, a0);
                a1 = fmaf(whh[1][1], hA1, a1);
                a2 = fmaf(whh[2][1], hA1, a2);
                c0 = fmaf(whh[0][1], hB1, c0);
                c1 = fmaf(whh[1][1], hB1, c1);
                c2 = fmaf(whh[2][1], hB1, c2);
                a0 = fmaf(whh[0][2], hA2, a0);
                a1 = fmaf(whh[1][2], hA2, a1);
                a2 = fmaf(whh[2][2], hA2, a2);
                c0 = fmaf(whh[0][2], hB2, c0);
                c1 = fmaf(whh[1][2], hB2, c1);
                c2 = fmaf(whh[2][2], hB2, c2);

                hA0 = fmaxf(a0, 0.0f); hA1 = fmaxf(a1, 0.0f); hA2 = fmaxf(a2, 0.0f);
                hB0 = fmaxf(c0, 0.0f); hB1 = fmaxf(c1, 0.0f); hB2 = fmaxf(c2, 0.0f);

                const size_t o = ((size_t)(t0 + k + 1) * BATCH + bA) * HID;
                __stcs((float2*)(outs + o),     make_float2(hA0, hA1));
                __stcs((float2*)(outs + o + 2), make_float2(hA2, hB0));
                __stcs((float2*)(outs + o + 4), make_float2(hB1, hB2));
            }
        }

        // Refill this stage for group g + STAGES - 1.
        const int gnext = g + STAGES - 1;
        if (gnext < NGRP) {
            const int ns = gnext & (STAGES - 1);
#pragma unroll
            for (int k = 0; k < UNR; k++) {
                const size_t src = (size_t)(gnext * UNR + k) * BATCH + bA;
                cp_async16(&xs[ns][k][0][lane], &xv[src]);
                cp_async16(&xs[ns][k][1][lane], &xv[src + 1]);
            }
        }
        cp_async_commit();  // uniform group accounting on the tail
    }

    hlast[bA * HID + 0] = hA0;
    hlast[bA * HID + 1] = hA1;
    hlast[bA * HID + 2] = hA2;
    hlast[bA * HID + 3] = hB0;
    hlast[bA * HID + 4] = hB1;
    hlast[bA * HID + 5] = hB2;
}

extern "C" void kernel_launch(void* const* d_in, const int* in_sizes, int n_in,
                              void* d_out, int out_size)
{
    const float* x    = (const float*)d_in[0];
    const float* h0   = (const float*)d_in[1];
    const float* W_ih = (const float*)d_in[2];
    const float* W_hh = (const float*)d_in[3];
    const float* b_ih = (const float*)d_in[4];
    const float* b_hh = (const float*)d_in[5];
    float* out = (float*)d_out;

    // 2048 chain pairs, one per thread; one warp per block, sync-free.
    rnn_relu_kernel<<<NPAIR / 32, 32>>>(x, h0, W_ih, W_hh, b_ih, b_hh, out);
}

// round 15
// speedup vs baseline: 2.0367x; 2.0367x over previous
#include <cuda_runtime.h>
#include <cstdint>

#define SEQ    2048
#define BATCH  4096
#define IN     4
#define HID    3
#define UNR    32                 // timesteps per pipeline stage (R6: 16)
#define STAGES 3                  // smem ring depth (R6: 4) -> 48 KB static
#define NGRP   (SEQ / UNR)        // 64 groups

typedef unsigned long long u64;

// ---- packed f32x2 helpers (Blackwell) ----
__device__ __forceinline__ u64 pack2(float lo, float hi) {
    u64 r; asm("mov.b64 %0, {%1, %2};" : "=l"(r) : "f"(lo), "f"(hi)); return r;
}
__device__ __forceinline__ u64 bcast2(float v) {
    u64 r; asm("mov.b64 %0, {%1, %1};" : "=l"(r) : "f"(v)); return r;
}
__device__ __forceinline__ u64 fma2(u64 a, u64 b, u64 c) {
    u64 d; asm("fma.rn.f32x2 %0, %1, %2, %3;" : "=l"(d) : "l"(a), "l"(b), "l"(c)); return d;
}
__device__ __forceinline__ float2 unpack2(u64 v) {
    float2 r; asm("mov.b64 {%0, %1}, %2;" : "=f"(r.x), "=f"(r.y) : "l"(v)); return r;
}

// ---- cp.async ----
__device__ __forceinline__ void cp_async16(void* smem_dst, const void* gmem_src) {
    uint32_t s;
    asm("{ .reg .u64 t; cvta.to.shared.u64 t, %1; cvt.u32.u64 %0, t; }"
        : "=r"(s) : "l"(smem_dst));
    asm volatile("cp.async.ca.shared.global [%0], [%1], 16;"
                 :: "r"(s), "l"(gmem_src) : "memory");
}
__device__ __forceinline__ void cp_async_commit() {
    asm volatile("cp.async.commit_group;" ::: "memory");
}
template <int N>
__device__ __forceinline__ void cp_async_wait() {
    asm volatile("cp.async.wait_group %0;" :: "n"(N) : "memory");
}

__global__ void __launch_bounds__(32, 1)
rnn_relu_kernel(const float* __restrict__ x,      // [SEQ, BATCH, 4]
                const float* __restrict__ h0,     // [1, BATCH, 3]
                const float* __restrict__ W_ih,   // [3, 4]
                const float* __restrict__ W_hh,   // [3, 3]
                const float* __restrict__ b_ih,   // [3]
                const float* __restrict__ b_hh,   // [3]
                float* __restrict__ out)
{
    // One warp per block; each thread owns one batch chain. Sync-free.
    __shared__ float4 xs[STAGES][UNR][32];   // 48 KB (exactly the static limit)

    const int lane = threadIdx.x;
    const int b = blockIdx.x * 32 + lane;

    // Pre-pack weights: hidden units (0,1) as f32x2 pairs, unit 2 scalar (R6).
    u64 wih01[IN], whh01[HID];
    float wih2[IN], whh2[HID];
#pragma unroll
    for (int i = 0; i < IN; i++) {
        wih01[i] = pack2(W_ih[0 * IN + i], W_ih[1 * IN + i]);
        wih2[i]  = W_ih[2 * IN + i];
    }
#pragma unroll
    for (int i = 0; i < HID; i++) {
        whh01[i] = pack2(W_hh[0 * HID + i], W_hh[1 * HID + i]);
        whh2[i]  = W_hh[2 * HID + i];
    }
    const u64   bias01 = pack2(b_ih[0] + b_hh[0], b_ih[1] + b_hh[1]);
    const float bias2  = b_ih[2] + b_hh[2];

    float ha = h0[b * HID + 0];
    float hb = h0[b * HID + 1];
    float hc = h0[b * HID + 2];

    const float4* __restrict__ xv = (const float4*)x;  // [SEQ][BATCH]
    float* __restrict__ outs  = out;
    float* __restrict__ hlast = out + (size_t)SEQ * BATCH * HID;

    // Prime STAGES-1 = 2 stages (64 timesteps of lookahead).
#pragma unroll
    for (int s = 0; s < STAGES - 1; s++) {
#pragma unroll
        for (int k = 0; k < UNR; k++)
            cp_async16(&xs[s][k][lane], &xv[(size_t)(s * UNR + k) * BATCH + b]);
        cp_async_commit();
    }

    // Rolling stage counters (avoid %3): group g lives in stage g mod 3;
    // refill target = stage of group g+2 = (stage+2) mod 3.
    int stage = 0;
    int fill  = STAGES - 1;   // (0+2) mod 3 = 2

    for (int g = 0; g < NGRP; g++) {
        cp_async_wait<STAGES - 2>();   // group g complete (self-written smem)

        const int t0 = g * UNR;
#pragma unroll
        for (int k = 0; k < UNR; k++) {
            const float4 xt = xs[stage][k][lane];

            // Input projection (off the serial chain): units (0,1) packed.
            u64 p01 = fma2(wih01[0], bcast2(xt.x), bias01);
            p01 = fma2(wih01[1], bcast2(xt.y), p01);
            p01 = fma2(wih01[2], bcast2(xt.z), p01);
            p01 = fma2(wih01[3], bcast2(xt.w), p01);
            float p2 = fmaf(wih2[0], xt.x, bias2);
            p2 = fmaf(wih2[1], xt.y, p2);
            p2 = fmaf(wih2[2], xt.z, p2);
            p2 = fmaf(wih2[3], xt.w, p2);

            // Recurrent update (packed units (0,1) + scalar unit 2 — R6 exact).
            u64 a01 = fma2(whh01[0], bcast2(ha), p01);
            a01 = fma2(whh01[1], bcast2(hb), a01);
            a01 = fma2(whh01[2], bcast2(hc), a01);
            float a2 = fmaf(whh2[0], ha, p2);
            a2 = fmaf(whh2[1], hb, a2);
            a2 = fmaf(whh2[2], hc, a2);

            const float2 a = unpack2(a01);
            ha = fmaxf(a.x, 0.0f);
            hb = fmaxf(a.y, 0.0f);
            hc = fmaxf(a2, 0.0f);

            const size_t o = ((size_t)(t0 + k) * BATCH + b) * HID;
            __stcs(outs + o + 0, ha);   // streaming: never re-read
            __stcs(outs + o + 1, hb);
            __stcs(outs + o + 2, hc);
        }

        // Refill stage `fill` with group g + STAGES - 1.
        const int gnext = g + STAGES - 1;
        if (gnext < NGRP) {
#pragma unroll
            for (int k = 0; k < UNR; k++)
                cp_async16(&xs[fill][k][lane],
                           &xv[(size_t)(gnext * UNR + k) * BATCH + b]);
        }
        cp_async_commit();  // uniform group accounting on the tail

        stage = (stage == STAGES - 1) ? 0 : stage + 1;
        fill  = (fill  == STAGES - 1) ? 0 : fill  + 1;
    }

    hlast[b * HID + 0] = ha;
    hlast[b * HID + 1] = hb;
    hlast[b * HID + 2] = hc;
}

extern "C" void kernel_launch(void* const* d_in, const int* in_sizes, int n_in,
                              void* d_out, int out_size)
{
    const float* x    = (const float*)d_in[0];
    const float* h0   = (const float*)d_in[1];
    const float* W_ih = (const float*)d_in[2];
    const float* W_hh = (const float*)d_in[3];
    const float* b_ih = (const float*)d_in[4];
    const float* b_hh = (const float*)d_in[5];
    float* out = (float*)d_out;

    rnn_relu_kernel<<<BATCH / 32, 32>>>(x, h0, W_ih, W_hh, b_ih, b_hh, out);
}

// round 16
// speedup vs baseline: 2.0495x; 1.0063x over previous
#include <cuda_runtime.h>
#include <cstdint>

#define SEQ    2048
#define BATCH  4096
#define IN     4
#define HID    3
#define UNR    32                 // timesteps per pipeline stage
#define STAGES 3                  // smem ring depth -> 48 KB static
#define NGRP   (SEQ / UNR)        // 64 groups

// ---- cp.async ----
__device__ __forceinline__ void cp_async16(void* smem_dst, const void* gmem_src) {
    uint32_t s;
    asm("{ .reg .u64 t; cvta.to.shared.u64 t, %1; cvt.u32.u64 %0, t; }"
        : "=r"(s) : "l"(smem_dst));
    asm volatile("cp.async.ca.shared.global [%0], [%1], 16;"
                 :: "r"(s), "l"(gmem_src) : "memory");
}
__device__ __forceinline__ void cp_async_commit() {
    asm volatile("cp.async.commit_group;" ::: "memory");
}
template <int N>
__device__ __forceinline__ void cp_async_wait() {
    asm volatile("cp.async.wait_group %0;" :: "n"(N) : "memory");
}

__global__ void __launch_bounds__(32, 1)
rnn_relu_kernel(const float* __restrict__ x,      // [SEQ, BATCH, 4]
                const float* __restrict__ h0,     // [1, BATCH, 3]
                const float* __restrict__ W_ih,   // [3, 4]
                const float* __restrict__ W_hh,   // [3, 3]
                const float* __restrict__ b_ih,   // [3]
                const float* __restrict__ b_hh,   // [3]
                float* __restrict__ out)
{
    // One warp per block; each thread owns one batch chain. Sync-free.
    __shared__ float4 xs[STAGES][UNR][32];   // 48 KB

    const int lane = threadIdx.x;
    const int b = blockIdx.x * 32 + lane;

    // All-scalar weights: zero per-iter pack/unpack movs, 16-cyc serial chain.
    float wih[HID][IN];
    float whh[HID][HID];
    float bias[HID];
#pragma unroll
    for (int j = 0; j < HID; j++) {
#pragma unroll
        for (int i = 0; i < IN; i++) wih[j][i] = W_ih[j * IN + i];
#pragma unroll
        for (int i = 0; i < HID; i++) whh[j][i] = W_hh[j * HID + i];
        bias[j] = b_ih[j] + b_hh[j];
    }

    float ha = h0[b * HID + 0];
    float hb = h0[b * HID + 1];
    float hc = h0[b * HID + 2];

    const float4* __restrict__ xv = (const float4*)x;  // [SEQ][BATCH]
    float* __restrict__ outs  = out;
    float* __restrict__ hlast = out + (size_t)SEQ * BATCH * HID;

    // Prime STAGES-1 = 2 stages (64 timesteps of lookahead).
#pragma unroll
    for (int s = 0; s < STAGES - 1; s++) {
#pragma unroll
        for (int k = 0; k < UNR; k++)
            cp_async16(&xs[s][k][lane], &xv[(size_t)(s * UNR + k) * BATCH + b]);
        cp_async_commit();
    }

    // Rolling stage counters (no %3): group g lives in stage g mod 3.
    int stage = 0;
    int fill  = STAGES - 1;

    for (int g = 0; g < NGRP; g++) {
        cp_async_wait<STAGES - 2>();   // group g complete (self-written smem)

        const int t0 = g * UNR;
#pragma unroll
        for (int k = 0; k < UNR; k++) {
            const float4 xt = xs[stage][k][lane];

            // Input projection (independent of h -> off the serial chain).
            float p0 = fmaf(wih[0][0], xt.x, bias[0]);
            float p1 = fmaf(wih[1][0], xt.x, bias[1]);
            float p2 = fmaf(wih[2][0], xt.x, bias[2]);
            p0 = fmaf(wih[0][1], xt.y, p0);
            p1 = fmaf(wih[1][1], xt.y, p1);
            p2 = fmaf(wih[2][1], xt.y, p2);
            p0 = fmaf(wih[0][2], xt.z, p0);
            p1 = fmaf(wih[1][2], xt.z, p1);
            p2 = fmaf(wih[2][2], xt.z, p2);
            p0 = fmaf(wih[0][3], xt.w, p0);
            p1 = fmaf(wih[1][3], xt.w, p1);
            p2 = fmaf(wih[2][3], xt.w, p2);

            // Recurrence: serial chain = 3 FFMA + FMNMX = 16 cyc, no movs.
            float a0 = fmaf(whh[0][0], ha, p0);
            float a1 = fmaf(whh[1][0], ha, p1);
            float a2 = fmaf(whh[2][0], ha, p2);
            a0 = fmaf(whh[0][1], hb, a0);
            a1 = fmaf(whh[1][1], hb, a1);
            a2 = fmaf(whh[2][1], hb, a2);
            a0 = fmaf(whh[0][2], hc, a0);
            a1 = fmaf(whh[1][2], hc, a1);
            a2 = fmaf(whh[2][2], hc, a2);

            ha = fmaxf(a0, 0.0f);
            hb = fmaxf(a1, 0.0f);
            hc = fmaxf(a2, 0.0f);

            const size_t o = ((size_t)(t0 + k) * BATCH + b) * HID;
            __stcs(outs + o + 0, ha);   // streaming: never re-read
            __stcs(outs + o + 1, hb);
            __stcs(outs + o + 2, hc);
        }

        // Refill stage `fill` with group g + STAGES - 1.
        const int gnext = g + STAGES - 1;
        if (gnext < NGRP) {
#pragma unroll
            for (int k = 0; k < UNR; k++)
                cp_async16(&xs[fill][k][lane],
                           &xv[(size_t)(gnext * UNR + k) * BATCH + b]);
        }
        cp_async_commit();  // uniform group accounting on the tail

        stage = (stage == STAGES - 1) ? 0 : stage + 1;
        fill  = (fill  == STAGES - 1) ? 0 : fill  + 1;
    }

    hlast[b * HID + 0] = ha;
    hlast[b * HID + 1] = hb;
    hlast[b * HID + 2] = hc;
}

extern "C" void kernel_launch(void* const* d_in, const int* in_sizes, int n_in,
                              void* d_out, int out_size)
{
    const float* x    = (const float*)d_in[0];
    const float* h0   = (const float*)d_in[1];
    const float* W_ih = (const float*)d_in[2];
    const float* W_hh = (const float*)d_in[3];
    const float* b_ih = (const float*)d_in[4];
    const float* b_hh = (const float*)d_in[5];
    float* out = (float*)d_out;

    rnn_relu_kernel<<<BATCH / 32, 32>>>(x, h0, W_ih, W_hh, b_ih, b_hh, out);
}